// round 16
// baseline (speedup 1.0000x reference)
#include <cuda_runtime.h>
#include <cuda_fp16.h>
#include <math.h>
#include <stdint.h>

// Problem constants
#define BB 4
#define TT 2048
#define EE 1024
#define HH 16
#define DD 64
#define MM (BB*TT)        // 8192
#define FF (4*EE)         // 4096
#define QKVS 3072         // merged qkv row stride

// ---------------- scratch (device globals; no allocation allowed) -------------
__device__ float  g_x [MM*EE];               // residual stream (fp32)
__device__ float  g_x2[MM*EE];
__device__ __half g_h [MM*EE];               // LN output (GEMM A)
__device__ __half g_qkv[(size_t)MM*QKVS];    // q|k|v merged (q pre-scaled)
__device__ __half g_o [MM*EE];               // attention output
__device__ __half g_m [(size_t)MM*FF];       // gelu(fc)
// pre-transposed weights (K-major [N,K], fp16)
__device__ __half g_wtqkv[(size_t)QKVS*EE];  // [3072,1024] (q rows pre-scaled)
__device__ float  g_bqkv [QKVS];             // merged bias (q pre-scaled)
__device__ __half g_wtp [EE*EE];
__device__ __half g_wtfc [(size_t)FF*EE];
__device__ __half g_wtout[(size_t)EE*FF];

// ---------------- helpers -----------------------------------------------------
__device__ __forceinline__ uint32_t smem_u32(const void* p) {
    uint32_t a;
    asm("{ .reg .u64 t; cvta.to.shared.u64 t, %1; cvt.u32.u64 %0, t; }" : "=r"(a) : "l"(p));
    return a;
}
__device__ __forceinline__ void cp16(uint32_t dst, const void* src) {
    asm volatile("cp.async.cg.shared.global [%0], [%1], 16;" :: "r"(dst), "l"(src));
}
#define CP_COMMIT() asm volatile("cp.async.commit_group;" ::: "memory")
#define CP_WAIT(n)  asm volatile("cp.async.wait_group %0;" :: "n"(n) : "memory")

// mma.sync m16n8k16 fp16 inputs, fp32 accumulate (sm_80+ base-target)
__device__ __forceinline__ void mma16(float* d, const uint32_t* a, const uint32_t* b) {
    asm volatile("mma.sync.aligned.m16n8k16.row.col.f32.f16.f16.f32 "
        "{%0,%1,%2,%3}, {%4,%5,%6,%7}, {%8,%9}, {%0,%1,%2,%3};"
        : "+f"(d[0]), "+f"(d[1]), "+f"(d[2]), "+f"(d[3])
        : "r"(a[0]), "r"(a[1]), "r"(a[2]), "r"(a[3]), "r"(b[0]), "r"(b[1]));
}
__device__ __forceinline__ void ldmx4(uint32_t& r0, uint32_t& r1, uint32_t& r2,
                                      uint32_t& r3, uint32_t addr) {
    asm volatile("ldmatrix.sync.aligned.m8n8.x4.shared.b16 {%0,%1,%2,%3}, [%4];"
        : "=r"(r0), "=r"(r1), "=r"(r2), "=r"(r3) : "r"(addr));
}
__device__ __forceinline__ void ldmx4t(uint32_t& r0, uint32_t& r1, uint32_t& r2,
                                       uint32_t& r3, uint32_t addr) {
    asm volatile("ldmatrix.sync.aligned.m8n8.x4.trans.shared.b16 {%0,%1,%2,%3}, [%4];"
        : "=r"(r0), "=r"(r1), "=r"(r2), "=r"(r3) : "r"(addr));
}
__device__ __forceinline__ uint32_t packh2(float a, float b) {
    __half2 h = __floats2half2_rn(a, b);
    return *(uint32_t*)&h;
}

// ---------------- fused prep kernel -------------------------------------------
// blocks [0,8192): embed+ln1     [8192,11264): qkv weight transpose
// [11264,11276): bias merge      [11276,20492): proj/fc/out transposes
__global__ __launch_bounds__(256) void prep_kernel(
    const int* __restrict__ ids, const float* __restrict__ wte,
    const float* __restrict__ wpe, const float* __restrict__ ln1g,
    const float* __restrict__ ln1b,
    const float* __restrict__ Wq, const float* __restrict__ Wk,
    const float* __restrict__ Wv, const float* __restrict__ bq,
    const float* __restrict__ bk, const float* __restrict__ bv,
    const float* __restrict__ Wp, const float* __restrict__ Wf,
    const float* __restrict__ Wo,
    float* __restrict__ X, __half* __restrict__ Y,
    __half* __restrict__ Wtqkv, float* __restrict__ bqkv,
    __half* __restrict__ Tp, __half* __restrict__ Tf, __half* __restrict__ To,
    float alpha)
{
    __shared__ float sh[32 * 33];
    const int bid = blockIdx.x, tid = threadIdx.x;

    if (bid < 8192) {
        // ---- embed + ln1 ----
        int row = bid;
        int t   = row & (TT - 1);
        int id  = ids[row];
        float4 a = ((const float4*)wte)[(size_t)id * 256 + tid];
        float4 p = ((const float4*)wpe)[(size_t)t  * 256 + tid];
        a.x += p.x; a.y += p.y; a.z += p.z; a.w += p.w;
        ((float4*)(X + ((size_t)row << 10)))[tid] = a;

        float s  = a.x + a.y + a.z + a.w;
        float sq = a.x*a.x + a.y*a.y + a.z*a.z + a.w*a.w;
        #pragma unroll
        for (int o = 16; o; o >>= 1) {
            s  += __shfl_xor_sync(0xffffffffu, s,  o);
            sq += __shfl_xor_sync(0xffffffffu, sq, o);
        }
        if ((tid & 31) == 0) { sh[tid >> 5] = s; sh[8 + (tid >> 5)] = sq; }
        __syncthreads();
        float ts = 0.f, tq = 0.f;
        #pragma unroll
        for (int i = 0; i < 8; i++) { ts += sh[i]; tq += sh[8 + i]; }
        float mean = ts * (1.f / 1024.f);
        float var  = tq * (1.f / 1024.f) - mean * mean;
        float inv  = rsqrtf(var + 1e-5f);
        float4 g4 = ((const float4*)ln1g)[tid];
        float4 b4 = ((const float4*)ln1b)[tid];
        __half2 h01 = __floats2half2_rn((a.x - mean) * inv * g4.x + b4.x,
                                        (a.y - mean) * inv * g4.y + b4.y);
        __half2 h23 = __floats2half2_rn((a.z - mean) * inv * g4.z + b4.z,
                                        (a.w - mean) * inv * g4.w + b4.w);
        uint2 o; o.x = *(uint32_t*)&h01; o.y = *(uint32_t*)&h23;
        ((uint2*)(Y + ((size_t)row << 10)))[tid] = o;
    } else if (bid < 11264) {
        // ---- qkv weight transpose (q section scaled by alpha) ----
        int b2 = bid - 8192;
        int bx = b2 & 1, by = (b2 >> 1) & 31, bz = b2 >> 6;
        int sec = bz >> 4, h = bz & 15;
        int k0 = by * 32, d0 = bx * 32;
        const float* W = (sec == 0) ? Wq : (sec == 1) ? Wk : Wv;
        float sc = (sec == 0) ? alpha : 1.f;
        const float* Wh = W + (size_t)h * EE * DD;
        int tx = tid & 31, ty = tid >> 5;
        #pragma unroll
        for (int i = ty; i < 32; i += 8) sh[i * 33 + tx] = Wh[(size_t)(k0 + i) * DD + d0 + tx];
        __syncthreads();
        #pragma unroll
        for (int i = ty; i < 32; i += 8)
            Wtqkv[(size_t)(sec * 1024 + h * DD + d0 + i) * EE + k0 + tx] =
                __float2half_rn(sh[tx * 33 + i] * sc);
    } else if (bid < 11276) {
        // ---- bias merge ----
        int i = (bid - 11264) * 256 + tid;     // 0..3071
        int sec = i >> 10, j = i & 1023;
        float v = (sec == 0) ? bq[j] * alpha : (sec == 1) ? bk[j] : bv[j];
        bqkv[i] = v;
    } else {
        // ---- proj / fc / out transposes ----
        int b3 = bid - 11276;
        const float* W; __half* Wt; int K, N, n0, k0;
        if (b3 < 1024) {
            W = Wp; Wt = Tp; K = 1024; N = 1024;
            n0 = (b3 & 31) * 32; k0 = (b3 >> 5) * 32;
        } else if (b3 < 5120) {
            int b = b3 - 1024;
            W = Wf; Wt = Tf; K = 1024; N = 4096;
            n0 = (b & 127) * 32; k0 = (b >> 7) * 32;
        } else {
            int b = b3 - 5120;
            W = Wo; Wt = To; K = 4096; N = 1024;
            n0 = (b & 31) * 32; k0 = (b >> 5) * 32;
        }
        int tx = tid & 31, ty = tid >> 5;
        #pragma unroll
        for (int i = ty; i < 32; i += 8) sh[i * 33 + tx] = W[(size_t)(k0 + i) * N + n0 + tx];
        __syncthreads();
        #pragma unroll
        for (int i = ty; i < 32; i += 8)
            Wt[(size_t)(n0 + i) * K + k0 + tx] = __float2half_rn(sh[tx * 33 + i]);
    }
}

// ---------------- layernorm (fp32 in, fp16 out) -------------------------------
__global__ __launch_bounds__(256) void ln_kernel(
    const float* __restrict__ X, const float* __restrict__ G,
    const float* __restrict__ Bt, __half* __restrict__ Y)
{
    __shared__ float red[16];
    int row = blockIdx.x, tid = threadIdx.x;
    const float4* x4 = (const float4*)(X + ((size_t)row << 10));
    float4 a = x4[tid];
    float s  = a.x + a.y + a.z + a.w;
    float sq = a.x*a.x + a.y*a.y + a.z*a.z + a.w*a.w;
    #pragma unroll
    for (int o = 16; o; o >>= 1) {
        s  += __shfl_xor_sync(0xffffffffu, s,  o);
        sq += __shfl_xor_sync(0xffffffffu, sq, o);
    }
    if ((tid & 31) == 0) { red[tid >> 5] = s; red[8 + (tid >> 5)] = sq; }
    __syncthreads();
    float ts = 0.f, tq = 0.f;
    #pragma unroll
    for (int i = 0; i < 8; i++) { ts += red[i]; tq += red[8 + i]; }
    float mean = ts * (1.f / 1024.f);
    float var  = tq * (1.f / 1024.f) - mean * mean;
    float inv  = rsqrtf(var + 1e-5f);
    float4 g4 = ((const float4*)G)[tid];
    float4 b4 = ((const float4*)Bt)[tid];
    __half2 h01 = __floats2half2_rn((a.x - mean) * inv * g4.x + b4.x,
                                    (a.y - mean) * inv * g4.y + b4.y);
    __half2 h23 = __floats2half2_rn((a.z - mean) * inv * g4.z + b4.z,
                                    (a.w - mean) * inv * g4.w + b4.w);
    uint2 o; o.x = *(uint32_t*)&h01; o.y = *(uint32_t*)&h23;
    ((uint2*)(Y + ((size_t)row << 10)))[tid] = o;
}

// ---------------- mma.sync fp16 GEMM (persistent, CTA 256x128, BK=64) ---------
// 256 threads = 8 warps in 4(m) x 2(n); warp tile 64x64; 1 CTA/SM.
// Per 1024 MMAs: stage writes 55KB (vs 147KB for 128x128x2CTA) -> less crossbar.
#define PADH  72
#define PADB  144
#define GSTGB (384*PADB)       // A(256 rows) + B(128 rows) x 144B = 55296B
#define GSMEM (3*GSTGB)        // 165888B
#define GEMM_GRID 148

__device__ __forceinline__ void gcp_stage(
    uint32_t sbase, int s, const __half* __restrict__ A, const __half* __restrict__ Wt,
    int bm, int bn, int K, int k0, int tid)
{
    uint32_t sA = sbase + s * GSTGB;
    uint32_t sB = sA + 256 * PADB;
    #pragma unroll
    for (int e = 0; e < 8; e++) {          // A: 256 rows x 8 chunks
        int lin = tid + 256 * e;
        int r = lin >> 3, c = lin & 7;
        cp16(sA + r * PADB + c * 16, A + (size_t)(bm + r) * K + k0 + c * 8);
    }
    #pragma unroll
    for (int e = 0; e < 4; e++) {          // B: 128 rows x 8 chunks
        int lin = tid + 256 * e;
        int r = lin >> 3, c = lin & 7;
        cp16(sB + r * PADB + c * 16, Wt + (size_t)(bn + r) * K + k0 + c * 8);
    }
}

template<bool GELU_, bool RES, bool OUTH>
__global__ __launch_bounds__(256, 1) void tc_gemm(
    const __half* __restrict__ A, const __half* __restrict__ Wt,
    const float* __restrict__ bias, const float* __restrict__ Rp,
    void* __restrict__ Cv, int M, int N, int K)
{
    extern __shared__ __align__(16) char smc[];
    uint32_t sbase = smem_u32(smc);
    const int tid = threadIdx.x, wid = tid >> 5, lid = tid & 31;
    const int g = lid >> 2, t = lid & 3;
    const int warp_m = (wid & 3) * 64, warp_n = (wid >> 2) * 64;
    const int NT = K >> 6;                 // BK=64 stages
    const int mtiles = M >> 8;             // 256-row tiles
    const int total = mtiles * (N >> 7);

    // per-lane ldmatrix base offsets (within a stage)
    const uint32_t aOff = (uint32_t)((warp_m + (lid & 15)) * PADB + (lid >> 4) * 16);
    const uint32_t bOff = (uint32_t)(256 * PADB +
        (warp_n + (lid & 7) + ((lid & 16) ? 8 : 0)) * PADB + ((lid >> 3) & 1) * 16);

    for (int tile = blockIdx.x; tile < total; tile += gridDim.x) {
        const int bm = (tile % mtiles) * 256;
        const int bn = (tile / mtiles) * 128;

        float d[4][8][4];
        #pragma unroll
        for (int i = 0; i < 4; i++)
            #pragma unroll
            for (int j = 0; j < 8; j++)
                #pragma unroll
                for (int p = 0; p < 4; p++) d[i][j][p] = 0.f;

        gcp_stage(sbase, 0, A, Wt, bm, bn, K, 0,  tid); CP_COMMIT();
        gcp_stage(sbase, 1, A, Wt, bm, bn, K, 64, tid); CP_COMMIT();

        for (int kt = 0; kt < NT; kt++) {
            if (kt == NT - 1) { CP_WAIT(0); } else { CP_WAIT(1); }
            __syncthreads();
            if (kt + 2 < NT) {
                gcp_stage(sbase, (kt + 2) % 3, A, Wt, bm, bn, K, (kt + 2) * 64, tid);
                CP_COMMIT();
            }
            const uint32_t stg = sbase + (uint32_t)((kt % 3) * GSTGB);
            #pragma unroll
            for (int ks = 0; ks < 4; ks++) {          // four k16 steps per BK=64
                const uint32_t kb = ks * 32;
                uint32_t af[4][4], bf[8][2];
                #pragma unroll
                for (int mf = 0; mf < 4; mf++)
                    ldmx4(af[mf][0], af[mf][1], af[mf][2], af[mf][3],
                          stg + aOff + mf * 16 * PADB + kb);
                #pragma unroll
                for (int np = 0; np < 4; np++)
                    ldmx4(bf[2*np][0], bf[2*np][1], bf[2*np+1][0], bf[2*np+1][1],
                          stg + bOff + np * 16 * PADB + kb);
                #pragma unroll
                for (int mf = 0; mf < 4; mf++)
                    #pragma unroll
                    for (int nf = 0; nf < 8; nf++)
                        mma16(d[mf][nf], af[mf], bf[nf]);
            }
        }
        __syncthreads();   // mainloop reads done before next tile refill

        // epilogue
        #pragma unroll
        for (int mf = 0; mf < 4; mf++) {
            int row0 = bm + warp_m + mf * 16 + g;
            #pragma unroll
            for (int nf = 0; nf < 8; nf++) {
                int col = bn + warp_n + nf * 8 + 2 * t;
                float b0 = __ldg(bias + col), b1 = __ldg(bias + col + 1);
                #pragma unroll
                for (int p = 0; p < 2; p++) {
                    int m = row0 + p * 8;
                    float v0 = d[mf][nf][2 * p + 0] + b0;
                    float v1 = d[mf][nf][2 * p + 1] + b1;
                    if (GELU_) {
                        v0 = 0.5f * v0 * (1.f + erff(v0 * 0.70710678118654752f));
                        v1 = 0.5f * v1 * (1.f + erff(v1 * 0.70710678118654752f));
                    }
                    if (OUTH) {
                        __half2 hp = __floats2half2_rn(v0, v1);
                        *(__half2*)((__half*)Cv + (size_t)m * N + col) = hp;
                    } else {
                        if (RES) {
                            float2 rr = *(const float2*)(Rp + (size_t)m * N + col);
                            v0 += rr.x; v1 += rr.y;
                        }
                        float2 o; o.x = v0; o.y = v1;
                        *(float2*)((float*)Cv + (size_t)m * N + col) = o;
                    }
                }
            }
        }
    }
}

// ---------------- tensor-core flash attention (causal, fp16) ------------------
// P kept in registers (S C-frag layout == PV A-frag layout) + 3-stage KV ring
// with a single barrier per kv-tile (wait -> sync -> prefetch(kt+2) -> compute).
#define A_QS 0
#define A_KS (128*PADH)
#define A_VS (A_KS + 3*64*PADH)
#define A_ENDH (A_VS + 3*64*PADH)
#define ATT_SMEM (A_ENDH*2)

__device__ __forceinline__ void att_kv_stage(
    uint32_t sb, int stage, const __half* __restrict__ Kp,
    const __half* __restrict__ Vp, int kb2, int tid)
{
    #pragma unroll
    for (int i = 0; i < 4; i++) {
        int idx = tid + i * 256;
        int r = idx >> 4, c = idx & 7, kv = (idx >> 3) & 1;
        uint32_t dst = kv ? (uint32_t)(A_VS + stage * 64 * PADH + r * PADH)
                          : (uint32_t)(A_KS + stage * 64 * PADH + r * PADH);
        const __half* src = kv ? Vp : Kp;
        cp16(sb + dst * 2 + c * 16, src + (size_t)(kb2 + r) * QKVS + c * 8);
    }
}

__global__ __launch_bounds__(256) void attn_tc(
    const __half* __restrict__ QKV, __half* __restrict__ O)
{
    extern __shared__ __align__(16) char smc[];
    uint32_t sb = smem_u32(smc);
    const int qt = (int)gridDim.x - 1 - (int)blockIdx.x;
    const int h = blockIdx.y, b = blockIdx.z;
    const int tid = threadIdx.x, wid = tid >> 5, lid = tid & 31;
    const int g = lid >> 2, t = lid & 3;
    const int qbase = qt * 128;
    const size_t qkvbase = (size_t)(b * TT) * QKVS + (size_t)h * DD;
    const __half* Q  = QKV + qkvbase;
    const __half* Kp = QKV + qkvbase + 1024;
    const __half* Vp = QKV + qkvbase + 2048;
    const size_t obase = (size_t)(b * TT) * EE + (size_t)h * DD;
    const int lr0 = wid * 16 + g;
    const int nt = 2 * qt + 2;

    // A-pattern ldmatrix per-lane offset (Q tile; row = wid*16 + (lid&15))
    const uint32_t apOff = (uint32_t)((wid * 16 + (lid & 15)) * PADB + (lid >> 4) * 16);
    // B-pattern ldmatrix per-lane offset (K tiles)
    const uint32_t bkOff = (uint32_t)(((lid & 7) + ((lid & 16) ? 8 : 0)) * PADB
                                      + ((lid >> 3) & 1) * 16);

    // group: Q tile
    #pragma unroll
    for (int i = 0; i < 4; i++) {
        int idx = tid + i * 256;
        int r = idx >> 3, c = idx & 7;
        cp16(sb + (A_QS + r * PADH) * 2 + c * 16, Q + (size_t)(qbase + r) * QKVS + c * 8);
    }
    CP_COMMIT();
    // groups: kv tiles 0 and 1 (nt >= 2 always)
    att_kv_stage(sb, 0, Kp, Vp, 0, tid);  CP_COMMIT();
    att_kv_stage(sb, 1, Kp, Vp, 64, tid); CP_COMMIT();

    CP_WAIT(2);            // Q tile resident
    __syncthreads();

    uint32_t aQ[4][4];
    #pragma unroll
    for (int ks = 0; ks < 4; ks++)
        ldmx4(aQ[ks][0], aQ[ks][1], aQ[ks][2], aQ[ks][3],
              sb + A_QS * 2 + apOff + ks * 32);
    // Q region never overwritten (P lives in registers) -> no barrier needed

    float o[8][4];
    #pragma unroll
    for (int nf = 0; nf < 8; nf++) { o[nf][0]=0.f; o[nf][1]=0.f; o[nf][2]=0.f; o[nf][3]=0.f; }
    float m0 = -INFINITY, m1 = -INFINITY, l0 = 0.f, l1 = 0.f;

    for (int kt = 0; kt < nt; kt++) {
        if (kt + 1 < nt) { CP_WAIT(1); } else { CP_WAIT(0); }
        __syncthreads();   // kv(kt) ready AND all warps finished compute(kt-1)
        if (kt + 2 < nt) {
            att_kv_stage(sb, (kt + 2) % 3, Kp, Vp, (kt + 2) * 64, tid);
            CP_COMMIT();
        }

        const int ktb = kt * 64;
        if (ktb <= qbase + wid * 16 + 15) {
            const uint32_t Ksb = sb + (A_KS + (kt % 3) * 64 * PADH) * 2;
            const uint32_t Vsb = sb + (A_VS + (kt % 3) * 64 * PADH) * 2;

            float s[8][4];
            #pragma unroll
            for (int nf = 0; nf < 8; nf++) { s[nf][0]=0.f; s[nf][1]=0.f; s[nf][2]=0.f; s[nf][3]=0.f; }
            #pragma unroll
            for (int ks = 0; ks < 4; ks++) {
                #pragma unroll
                for (int np = 0; np < 4; np++) {
                    uint32_t bf0[2], bf1[2];
                    ldmx4(bf0[0], bf0[1], bf1[0], bf1[1],
                          Ksb + bkOff + np * 16 * PADB + ks * 32);
                    mma16(s[2*np],   aQ[ks], bf0);
                    mma16(s[2*np+1], aQ[ks], bf1);
                }
            }
            const int r0 = qbase + lr0, r1 = r0 + 8;
            if (ktb + 63 > qbase + wid * 16) {       // diagonal: mask
                #pragma unroll
                for (int nf = 0; nf < 8; nf++) {
                    int c0 = ktb + nf * 8 + 2 * t;
                    if (c0     > r0) s[nf][0] = -INFINITY;
                    if (c0 + 1 > r0) s[nf][1] = -INFINITY;
                    if (c0     > r1) s[nf][2] = -INFINITY;
                    if (c0 + 1 > r1) s[nf][3] = -INFINITY;
                }
            }
            float mx0 = -INFINITY, mx1 = -INFINITY;
            #pragma unroll
            for (int nf = 0; nf < 8; nf++) {
                mx0 = fmaxf(mx0, fmaxf(s[nf][0], s[nf][1]));
                mx1 = fmaxf(mx1, fmaxf(s[nf][2], s[nf][3]));
            }
            mx0 = fmaxf(mx0, __shfl_xor_sync(0xffffffffu, mx0, 1));
            mx0 = fmaxf(mx0, __shfl_xor_sync(0xffffffffu, mx0, 2));
            mx1 = fmaxf(mx1, __shfl_xor_sync(0xffffffffu, mx1, 1));
            mx1 = fmaxf(mx1, __shfl_xor_sync(0xffffffffu, mx1, 2));
            float nm0 = fmaxf(m0, mx0), nm1 = fmaxf(m1, mx1);
            float scl0 = exp2f(m0 - nm0), scl1 = exp2f(m1 - nm1);

            // exp in-place: s[][] becomes P (stays in registers)
            float ls0 = 0.f, ls1 = 0.f;
            #pragma unroll
            for (int nf = 0; nf < 8; nf++) {
                s[nf][0] = exp2f(s[nf][0] - nm0);
                s[nf][1] = exp2f(s[nf][1] - nm0);
                s[nf][2] = exp2f(s[nf][2] - nm1);
                s[nf][3] = exp2f(s[nf][3] - nm1);
                ls0 += s[nf][0] + s[nf][1]; ls1 += s[nf][2] + s[nf][3];
            }
            ls0 += __shfl_xor_sync(0xffffffffu, ls0, 1);
            ls0 += __shfl_xor_sync(0xffffffffu, ls0, 2);
            ls1 += __shfl_xor_sync(0xffffffffu, ls1, 1);
            ls1 += __shfl_xor_sync(0xffffffffu, ls1, 2);
            l0 = l0 * scl0 + ls0; l1 = l1 * scl1 + ls1;
            #pragma unroll
            for (int nf = 0; nf < 8; nf++) {
                o[nf][0] *= scl0; o[nf][1] *= scl0; o[nf][2] *= scl1; o[nf][3] *= scl1;
            }
            // O += P V : P A-frags packed directly from S C-frags (layout identity)
            const int lmq = lid >> 3, lmr = lid & 7;
            #pragma unroll
            for (int ks = 0; ks < 4; ks++) {
                uint32_t ap[4];
                ap[0] = packh2(s[2*ks][0],   s[2*ks][1]);
                ap[1] = packh2(s[2*ks][2],   s[2*ks][3]);
                ap[2] = packh2(s[2*ks+1][0], s[2*ks+1][1]);
                ap[3] = packh2(s[2*ks+1][2], s[2*ks+1][3]);
                #pragma unroll
                for (int nf2 = 0; nf2 < 4; nf2++) {
                    int s_off = ks * 16 + (lmq & 1) * 8 + lmr;
                    int d_off = nf2 * 16 + (lmq >> 1) * 8;
                    uint32_t r0v, r1v, r2v, r3v;
                    ldmx4t(r0v, r1v, r2v, r3v, Vsb + (s_off * PADH + d_off) * 2);
                    uint32_t bfa[2] = { r0v, r1v };
                    uint32_t bfb[2] = { r2v, r3v };
                    mma16(o[nf2 * 2],     ap, bfa);
                    mma16(o[nf2 * 2 + 1], ap, bfb);
                }
            }
            m0 = nm0; m1 = nm1;
        }
    }

    float inv0 = 1.f / l0, inv1 = 1.f / l1;
    #pragma unroll
    for (int nf = 0; nf < 8; nf++) {
        int c = nf * 8 + 2 * t;
        *(__half2*)(O + obase + (size_t)(qbase + lr0) * EE + c) =
            __floats2half2_rn(o[nf][0] * inv0, o[nf][1] * inv0);
        *(__half2*)(O + obase + (size_t)(qbase + lr0 + 8) * EE + c) =
            __floats2half2_rn(o[nf][2] * inv1, o[nf][3] * inv1);
    }
}

// ---------------- launch ------------------------------------------------------
extern "C" void kernel_launch(void* const* d_in, const int* in_sizes, int n_in,
                              void* d_out, int out_size)
{
    const int*   ids   = (const int*)  d_in[0];
    const float* wte   = (const float*)d_in[1];
    const float* wpe   = (const float*)d_in[2];
    const float* wq    = (const float*)d_in[3];
    const float* wk    = (const float*)d_in[4];
    const float* wv    = (const float*)d_in[5];
    const float* bq    = (const float*)d_in[6];
    const float* bk    = (const float*)d_in[7];
    const float* bv    = (const float*)d_in[8];
    const float* wproj = (const float*)d_in[9];
    const float* bproj = (const float*)d_in[10];
    const float* ln1g  = (const float*)d_in[11];
    const float* ln1b  = (const float*)d_in[12];
    const float* ln2g  = (const float*)d_in[13];
    const float* ln2b  = (const float*)d_in[14];
    const float* wfc   = (const float*)d_in[15];
    const float* bfc   = (const float*)d_in[16];
    const float* wout  = (const float*)d_in[17];
    const float* bout  = (const float*)d_in[18];
    float* out = (float*)d_out;

    float *x, *x2, *bqkv;
    __half *h, *qkv, *o, *mb;
    __half *wtqkv, *wtp, *wtfc, *wtout;
    cudaGetSymbolAddress((void**)&x,  g_x);
    cudaGetSymbolAddress((void**)&x2, g_x2);
    cudaGetSymbolAddress((void**)&h,  g_h);
    cudaGetSymbolAddress((void**)&qkv, g_qkv);
    cudaGetSymbolAddress((void**)&o,  g_o);
    cudaGetSymbolAddress((void**)&mb, g_m);
    cudaGetSymbolAddress((void**)&wtqkv, g_wtqkv);
    cudaGetSymbolAddress((void**)&bqkv,  g_bqkv);
    cudaGetSymbolAddress((void**)&wtp,   g_wtp);
    cudaGetSymbolAddress((void**)&wtfc,  g_wtfc);
    cudaGetSymbolAddress((void**)&wtout, g_wtout);

    cudaFuncSetAttribute(attn_tc, cudaFuncAttributeMaxDynamicSharedMemorySize, ATT_SMEM);
    cudaFuncSetAttribute(tc_gemm<false,false,true>,  cudaFuncAttributeMaxDynamicSharedMemorySize, GSMEM);
    cudaFuncSetAttribute(tc_gemm<false,true,false>,  cudaFuncAttributeMaxDynamicSharedMemorySize, GSMEM);
    cudaFuncSetAttribute(tc_gemm<true,false,true>,   cudaFuncAttributeMaxDynamicSharedMemorySize, GSMEM);

    const float alpha = 0.18033688011112042f;   // 0.125 * log2(e)

    // 0. fused prep: embed+ln1 + all weight transposes + bias merge
    prep_kernel<<<20492, 256>>>(ids, wte, wpe, ln1g, ln1b,
                                wq, wk, wv, bq, bk, bv,
                                wproj, wfc, wout,
                                x, h, wtqkv, bqkv, wtp, wtfc, wtout, alpha);
    // 1. merged qkv projection (N=3072)
    tc_gemm<false,false,true><<<GEMM_GRID, 256, GSMEM>>>(h, wtqkv, bqkv, nullptr, qkv, MM, QKVS, EE);
    // 2. causal flash attention
    attn_tc<<<dim3(TT / 128, HH, BB), 256, ATT_SMEM>>>(qkv, o);
    // 3. proj + residual -> x2
    tc_gemm<false,true,false><<<GEMM_GRID, 256, GSMEM>>>(o, wtp, bproj, x, x2, MM, EE, EE);
    // 4. ln2
    ln_kernel<<<MM, 256>>>(x2, ln2g, ln2b, h);
    // 5. fc + gelu -> m
    tc_gemm<true,false,true><<<GEMM_GRID, 256, GSMEM>>>(h, wtfc, bfc, nullptr, mb, MM, FF, EE);
    // 6. out proj + residual -> d_out
    tc_gemm<false,true,false><<<GEMM_GRID, 256, GSMEM>>>(mb, wtout, bout, x2, out, MM, EE, FF);
}

// round 17
// speedup vs baseline: 1.0664x; 1.0664x over previous
#include <cuda_runtime.h>
#include <cuda_fp16.h>
#include <math.h>
#include <stdint.h>

// Problem constants
#define BB 4
#define TT 2048
#define EE 1024
#define HH 16
#define DD 64
#define MM (BB*TT)        // 8192
#define FF (4*EE)         // 4096
#define QKVS 3072         // merged qkv row stride

// ---------------- scratch (device globals; no allocation allowed) -------------
__device__ float  g_x [MM*EE];               // residual stream (fp32)
__device__ float  g_x2[MM*EE];
__device__ __half g_h [MM*EE];               // LN output (GEMM A)
__device__ __half g_qkv[(size_t)MM*QKVS];    // q|k|v merged (q pre-scaled)
__device__ __half g_o [MM*EE];               // attention output
__device__ __half g_m [(size_t)MM*FF];       // gelu(fc)
// pre-transposed weights (K-major [N,K], fp16)
__device__ __half g_wtqkv[(size_t)QKVS*EE];  // [3072,1024] (q rows pre-scaled)
__device__ float  g_bqkv [QKVS];             // merged bias (q pre-scaled)
__device__ __half g_wtp [EE*EE];
__device__ __half g_wtfc [(size_t)FF*EE];
__device__ __half g_wtout[(size_t)EE*FF];

// ---------------- helpers -----------------------------------------------------
__device__ __forceinline__ uint32_t smem_u32(const void* p) {
    uint32_t a;
    asm("{ .reg .u64 t; cvta.to.shared.u64 t, %1; cvt.u32.u64 %0, t; }" : "=r"(a) : "l"(p));
    return a;
}
__device__ __forceinline__ void cp16(uint32_t dst, const void* src) {
    asm volatile("cp.async.cg.shared.global [%0], [%1], 16;" :: "r"(dst), "l"(src));
}
#define CP_COMMIT() asm volatile("cp.async.commit_group;" ::: "memory")
#define CP_WAIT(n)  asm volatile("cp.async.wait_group %0;" :: "n"(n) : "memory")

// mma.sync m16n8k16 fp16 inputs, fp32 accumulate (sm_80+ base-target)
__device__ __forceinline__ void mma16(float* d, const uint32_t* a, const uint32_t* b) {
    asm volatile("mma.sync.aligned.m16n8k16.row.col.f32.f16.f16.f32 "
        "{%0,%1,%2,%3}, {%4,%5,%6,%7}, {%8,%9}, {%0,%1,%2,%3};"
        : "+f"(d[0]), "+f"(d[1]), "+f"(d[2]), "+f"(d[3])
        : "r"(a[0]), "r"(a[1]), "r"(a[2]), "r"(a[3]), "r"(b[0]), "r"(b[1]));
}
__device__ __forceinline__ void ldmx4(uint32_t& r0, uint32_t& r1, uint32_t& r2,
                                      uint32_t& r3, uint32_t addr) {
    asm volatile("ldmatrix.sync.aligned.m8n8.x4.shared.b16 {%0,%1,%2,%3}, [%4];"
        : "=r"(r0), "=r"(r1), "=r"(r2), "=r"(r3) : "r"(addr));
}
__device__ __forceinline__ void ldmx4t(uint32_t& r0, uint32_t& r1, uint32_t& r2,
                                       uint32_t& r3, uint32_t addr) {
    asm volatile("ldmatrix.sync.aligned.m8n8.x4.trans.shared.b16 {%0,%1,%2,%3}, [%4];"
        : "=r"(r0), "=r"(r1), "=r"(r2), "=r"(r3) : "r"(addr));
}
__device__ __forceinline__ uint32_t packh2(float a, float b) {
    __half2 h = __floats2half2_rn(a, b);
    return *(uint32_t*)&h;
}
// single-MUFU exp2 / reciprocal (guaranteed fast path regardless of -use_fast_math)
__device__ __forceinline__ float ex2(float x) {
    float y; asm("ex2.approx.ftz.f32 %0, %1;" : "=f"(y) : "f"(x)); return y;
}
__device__ __forceinline__ float rcpa(float x) {
    float y; asm("rcp.approx.ftz.f32 %0, %1;" : "=f"(y) : "f"(x)); return y;
}

// ---------------- fused prep kernel -------------------------------------------
// blocks [0,8192): embed+ln1     [8192,11264): qkv weight transpose
// [11264,11276): bias merge      [11276,20492): proj/fc/out transposes
__global__ __launch_bounds__(256) void prep_kernel(
    const int* __restrict__ ids, const float* __restrict__ wte,
    const float* __restrict__ wpe, const float* __restrict__ ln1g,
    const float* __restrict__ ln1b,
    const float* __restrict__ Wq, const float* __restrict__ Wk,
    const float* __restrict__ Wv, const float* __restrict__ bq,
    const float* __restrict__ bk, const float* __restrict__ bv,
    const float* __restrict__ Wp, const float* __restrict__ Wf,
    const float* __restrict__ Wo,
    float* __restrict__ X, __half* __restrict__ Y,
    __half* __restrict__ Wtqkv, float* __restrict__ bqkv,
    __half* __restrict__ Tp, __half* __restrict__ Tf, __half* __restrict__ To,
    float alpha)
{
    __shared__ float sh[32 * 33];
    const int bid = blockIdx.x, tid = threadIdx.x;

    if (bid < 8192) {
        // ---- embed + ln1 ----
        int row = bid;
        int t   = row & (TT - 1);
        int id  = ids[row];
        float4 a = ((const float4*)wte)[(size_t)id * 256 + tid];
        float4 p = ((const float4*)wpe)[(size_t)t  * 256 + tid];
        a.x += p.x; a.y += p.y; a.z += p.z; a.w += p.w;
        ((float4*)(X + ((size_t)row << 10)))[tid] = a;

        float s  = a.x + a.y + a.z + a.w;
        float sq = a.x*a.x + a.y*a.y + a.z*a.z + a.w*a.w;
        #pragma unroll
        for (int o = 16; o; o >>= 1) {
            s  += __shfl_xor_sync(0xffffffffu, s,  o);
            sq += __shfl_xor_sync(0xffffffffu, sq, o);
        }
        if ((tid & 31) == 0) { sh[tid >> 5] = s; sh[8 + (tid >> 5)] = sq; }
        __syncthreads();
        float ts = 0.f, tq = 0.f;
        #pragma unroll
        for (int i = 0; i < 8; i++) { ts += sh[i]; tq += sh[8 + i]; }
        float mean = ts * (1.f / 1024.f);
        float var  = tq * (1.f / 1024.f) - mean * mean;
        float inv  = rsqrtf(var + 1e-5f);
        float4 g4 = ((const float4*)ln1g)[tid];
        float4 b4 = ((const float4*)ln1b)[tid];
        __half2 h01 = __floats2half2_rn((a.x - mean) * inv * g4.x + b4.x,
                                        (a.y - mean) * inv * g4.y + b4.y);
        __half2 h23 = __floats2half2_rn((a.z - mean) * inv * g4.z + b4.z,
                                        (a.w - mean) * inv * g4.w + b4.w);
        uint2 o; o.x = *(uint32_t*)&h01; o.y = *(uint32_t*)&h23;
        ((uint2*)(Y + ((size_t)row << 10)))[tid] = o;
    } else if (bid < 11264) {
        // ---- qkv weight transpose (q section scaled by alpha) ----
        int b2 = bid - 8192;
        int bx = b2 & 1, by = (b2 >> 1) & 31, bz = b2 >> 6;
        int sec = bz >> 4, h = bz & 15;
        int k0 = by * 32, d0 = bx * 32;
        const float* W = (sec == 0) ? Wq : (sec == 1) ? Wk : Wv;
        float sc = (sec == 0) ? alpha : 1.f;
        const float* Wh = W + (size_t)h * EE * DD;
        int tx = tid & 31, ty = tid >> 5;
        #pragma unroll
        for (int i = ty; i < 32; i += 8) sh[i * 33 + tx] = Wh[(size_t)(k0 + i) * DD + d0 + tx];
        __syncthreads();
        #pragma unroll
        for (int i = ty; i < 32; i += 8)
            Wtqkv[(size_t)(sec * 1024 + h * DD + d0 + i) * EE + k0 + tx] =
                __float2half_rn(sh[tx * 33 + i] * sc);
    } else if (bid < 11276) {
        // ---- bias merge ----
        int i = (bid - 11264) * 256 + tid;     // 0..3071
        int sec = i >> 10, j = i & 1023;
        float v = (sec == 0) ? bq[j] * alpha : (sec == 1) ? bk[j] : bv[j];
        bqkv[i] = v;
    } else {
        // ---- proj / fc / out transposes ----
        int b3 = bid - 11276;
        const float* W; __half* Wt; int K, N, n0, k0;
        if (b3 < 1024) {
            W = Wp; Wt = Tp; K = 1024; N = 1024;
            n0 = (b3 & 31) * 32; k0 = (b3 >> 5) * 32;
        } else if (b3 < 5120) {
            int b = b3 - 1024;
            W = Wf; Wt = Tf; K = 1024; N = 4096;
            n0 = (b & 127) * 32; k0 = (b >> 7) * 32;
        } else {
            int b = b3 - 5120;
            W = Wo; Wt = To; K = 4096; N = 1024;
            n0 = (b & 31) * 32; k0 = (b >> 5) * 32;
        }
        int tx = tid & 31, ty = tid >> 5;
        #pragma unroll
        for (int i = ty; i < 32; i += 8) sh[i * 33 + tx] = W[(size_t)(k0 + i) * N + n0 + tx];
        __syncthreads();
        #pragma unroll
        for (int i = ty; i < 32; i += 8)
            Wt[(size_t)(n0 + i) * K + k0 + tx] = __float2half_rn(sh[tx * 33 + i]);
    }
}

// ---------------- layernorm (fp32 in, fp16 out) -------------------------------
__global__ __launch_bounds__(256) void ln_kernel(
    const float* __restrict__ X, const float* __restrict__ G,
    const float* __restrict__ Bt, __half* __restrict__ Y)
{
    __shared__ float red[16];
    int row = blockIdx.x, tid = threadIdx.x;
    const float4* x4 = (const float4*)(X + ((size_t)row << 10));
    float4 a = x4[tid];
    float s  = a.x + a.y + a.z + a.w;
    float sq = a.x*a.x + a.y*a.y + a.z*a.z + a.w*a.w;
    #pragma unroll
    for (int o = 16; o; o >>= 1) {
        s  += __shfl_xor_sync(0xffffffffu, s,  o);
        sq += __shfl_xor_sync(0xffffffffu, sq, o);
    }
    if ((tid & 31) == 0) { red[tid >> 5] = s; red[8 + (tid >> 5)] = sq; }
    __syncthreads();
    float ts = 0.f, tq = 0.f;
    #pragma unroll
    for (int i = 0; i < 8; i++) { ts += red[i]; tq += red[8 + i]; }
    float mean = ts * (1.f / 1024.f);
    float var  = tq * (1.f / 1024.f) - mean * mean;
    float inv  = rsqrtf(var + 1e-5f);
    float4 g4 = ((const float4*)G)[tid];
    float4 b4 = ((const float4*)Bt)[tid];
    __half2 h01 = __floats2half2_rn((a.x - mean) * inv * g4.x + b4.x,
                                    (a.y - mean) * inv * g4.y + b4.y);
    __half2 h23 = __floats2half2_rn((a.z - mean) * inv * g4.z + b4.z,
                                    (a.w - mean) * inv * g4.w + b4.w);
    uint2 o; o.x = *(uint32_t*)&h01; o.y = *(uint32_t*)&h23;
    ((uint2*)(Y + ((size_t)row << 10)))[tid] = o;
}

// ---------------- mma.sync fp16 GEMM (R14: persistent, BK=64, 4 warps 64x64) --
#define PADH  72
#define PADB  144
#define GSTGB (256*PADB)       // A(128 rows x 144B) + B(128 rows x 144B) = 36864B
#define GSMEM (3*GSTGB)
#define GEMM_GRID 296

__device__ __forceinline__ void gcp_stage(
    uint32_t sbase, int s, const __half* __restrict__ A, const __half* __restrict__ Wt,
    int bm, int bn, int K, int k0, int tid)
{
    uint32_t sA = sbase + s * GSTGB;
    uint32_t sB = sA + 128 * PADB;
    #pragma unroll
    for (int e = 0; e < 8; e++) {
        int lin = tid + 128 * e;           // 0..1023 (128 rows x 8 chunks)
        int r = lin >> 3, c = lin & 7;
        cp16(sA + r * PADB + c * 16, A  + (size_t)(bm + r) * K + k0 + c * 8);
        cp16(sB + r * PADB + c * 16, Wt + (size_t)(bn + r) * K + k0 + c * 8);
    }
}

template<bool GELU_, bool RES, bool OUTH>
__global__ __launch_bounds__(128) void tc_gemm(
    const __half* __restrict__ A, const __half* __restrict__ Wt,
    const float* __restrict__ bias, const float* __restrict__ Rp,
    void* __restrict__ Cv, int M, int N, int K)
{
    extern __shared__ __align__(16) char smc[];
    uint32_t sbase = smem_u32(smc);
    const int tid = threadIdx.x, wid = tid >> 5, lid = tid & 31;
    const int g = lid >> 2, t = lid & 3;
    const int warp_m = (wid & 1) * 64, warp_n = (wid >> 1) * 64;
    const int NT = K >> 6;                 // BK=64 stages
    const int mtiles = M >> 7;
    const int total = mtiles * (N >> 7);

    // per-lane ldmatrix base offsets (within a stage)
    const uint32_t aOff = (uint32_t)((warp_m + (lid & 15)) * PADB + (lid >> 4) * 16);
    const uint32_t bOff = (uint32_t)(128 * PADB +
        (warp_n + (lid & 7) + ((lid & 16) ? 8 : 0)) * PADB + ((lid >> 3) & 1) * 16);

    for (int tile = blockIdx.x; tile < total; tile += gridDim.x) {
        const int bm = (tile % mtiles) * 128;
        const int bn = (tile / mtiles) * 128;

        float d[4][8][4];
        #pragma unroll
        for (int i = 0; i < 4; i++)
            #pragma unroll
            for (int j = 0; j < 8; j++)
                #pragma unroll
                for (int p = 0; p < 4; p++) d[i][j][p] = 0.f;

        gcp_stage(sbase, 0, A, Wt, bm, bn, K, 0,  tid); CP_COMMIT();
        gcp_stage(sbase, 1, A, Wt, bm, bn, K, 64, tid); CP_COMMIT();

        for (int kt = 0; kt < NT; kt++) {
            if (kt == NT - 1) { CP_WAIT(0); } else { CP_WAIT(1); }
            __syncthreads();
            if (kt + 2 < NT) {
                gcp_stage(sbase, (kt + 2) % 3, A, Wt, bm, bn, K, (kt + 2) * 64, tid);
                CP_COMMIT();
            }
            const uint32_t stg = sbase + (uint32_t)((kt % 3) * GSTGB);
            #pragma unroll
            for (int ks = 0; ks < 4; ks++) {          // four k16 steps per BK=64
                const uint32_t kb = ks * 32;
                uint32_t af[4][4], bf[8][2];
                #pragma unroll
                for (int mf = 0; mf < 4; mf++)
                    ldmx4(af[mf][0], af[mf][1], af[mf][2], af[mf][3],
                          stg + aOff + mf * 16 * PADB + kb);
                #pragma unroll
                for (int np = 0; np < 4; np++)
                    ldmx4(bf[2*np][0], bf[2*np][1], bf[2*np+1][0], bf[2*np+1][1],
                          stg + bOff + np * 16 * PADB + kb);
                #pragma unroll
                for (int mf = 0; mf < 4; mf++)
                    #pragma unroll
                    for (int nf = 0; nf < 8; nf++)
                        mma16(d[mf][nf], af[mf], bf[nf]);
            }
        }
        __syncthreads();   // mainloop reads done before next tile refill

        // epilogue
        #pragma unroll
        for (int mf = 0; mf < 4; mf++) {
            int row0 = bm + warp_m + mf * 16 + g;
            #pragma unroll
            for (int nf = 0; nf < 8; nf++) {
                int col = bn + warp_n + nf * 8 + 2 * t;
                float b0 = __ldg(bias + col), b1 = __ldg(bias + col + 1);
                #pragma unroll
                for (int p = 0; p < 2; p++) {
                    int m = row0 + p * 8;
                    float v0 = d[mf][nf][2 * p + 0] + b0;
                    float v1 = d[mf][nf][2 * p + 1] + b1;
                    if (GELU_) {
                        v0 = 0.5f * v0 * (1.f + erff(v0 * 0.70710678118654752f));
                        v1 = 0.5f * v1 * (1.f + erff(v1 * 0.70710678118654752f));
                    }
                    if (OUTH) {
                        __half2 hp = __floats2half2_rn(v0, v1);
                        *(__half2*)((__half*)Cv + (size_t)m * N + col) = hp;
                    } else {
                        if (RES) {
                            float2 rr = *(const float2*)(Rp + (size_t)m * N + col);
                            v0 += rr.x; v1 += rr.y;
                        }
                        float2 o; o.x = v0; o.y = v1;
                        *(float2*)((float*)Cv + (size_t)m * N + col) = o;
                    }
                }
            }
        }
    }
}

// ---------------- tensor-core flash attention (causal, fp16) ------------------
// P kept in registers (S C-frag layout == PV A-frag layout) + 3-stage KV ring
// with a single barrier per kv-tile. Softmax via raw MUFU ex2/rcp.
#define A_QS 0
#define A_KS (128*PADH)
#define A_VS (A_KS + 3*64*PADH)
#define A_ENDH (A_VS + 3*64*PADH)
#define ATT_SMEM (A_ENDH*2)

__device__ __forceinline__ void att_kv_stage(
    uint32_t sb, int stage, const __half* __restrict__ Kp,
    const __half* __restrict__ Vp, int kb2, int tid)
{
    #pragma unroll
    for (int i = 0; i < 4; i++) {
        int idx = tid + i * 256;
        int r = idx >> 4, c = idx & 7, kv = (idx >> 3) & 1;
        uint32_t dst = kv ? (uint32_t)(A_VS + stage * 64 * PADH + r * PADH)
                          : (uint32_t)(A_KS + stage * 64 * PADH + r * PADH);
        const __half* src = kv ? Vp : Kp;
        cp16(sb + dst * 2 + c * 16, src + (size_t)(kb2 + r) * QKVS + c * 8);
    }
}

__global__ __launch_bounds__(256) void attn_tc(
    const __half* __restrict__ QKV, __half* __restrict__ O)
{
    extern __shared__ __align__(16) char smc[];
    uint32_t sb = smem_u32(smc);
    const int qt = (int)gridDim.x - 1 - (int)blockIdx.x;
    const int h = blockIdx.y, b = blockIdx.z;
    const int tid = threadIdx.x, wid = tid >> 5, lid = tid & 31;
    const int g = lid >> 2, t = lid & 3;
    const int qbase = qt * 128;
    const size_t qkvbase = (size_t)(b * TT) * QKVS + (size_t)h * DD;
    const __half* Q  = QKV + qkvbase;
    const __half* Kp = QKV + qkvbase + 1024;
    const __half* Vp = QKV + qkvbase + 2048;
    const size_t obase = (size_t)(b * TT) * EE + (size_t)h * DD;
    const int lr0 = wid * 16 + g;
    const int nt = 2 * qt + 2;

    // A-pattern ldmatrix per-lane offset (Q tile; row = wid*16 + (lid&15))
    const uint32_t apOff = (uint32_t)((wid * 16 + (lid & 15)) * PADB + (lid >> 4) * 16);
    // B-pattern ldmatrix per-lane offset (K tiles)
    const uint32_t bkOff = (uint32_t)(((lid & 7) + ((lid & 16) ? 8 : 0)) * PADB
                                      + ((lid >> 3) & 1) * 16);

    // group: Q tile
    #pragma unroll
    for (int i = 0; i < 4; i++) {
        int idx = tid + i * 256;
        int r = idx >> 3, c = idx & 7;
        cp16(sb + (A_QS + r * PADH) * 2 + c * 16, Q + (size_t)(qbase + r) * QKVS + c * 8);
    }
    CP_COMMIT();
    // groups: kv tiles 0 and 1 (nt >= 2 always)
    att_kv_stage(sb, 0, Kp, Vp, 0, tid);  CP_COMMIT();
    att_kv_stage(sb, 1, Kp, Vp, 64, tid); CP_COMMIT();

    CP_WAIT(2);            // Q tile resident
    __syncthreads();

    uint32_t aQ[4][4];
    #pragma unroll
    for (int ks = 0; ks < 4; ks++)
        ldmx4(aQ[ks][0], aQ[ks][1], aQ[ks][2], aQ[ks][3],
              sb + A_QS * 2 + apOff + ks * 32);
    // Q region never overwritten (P lives in registers) -> no barrier needed

    float o[8][4];
    #pragma unroll
    for (int nf = 0; nf < 8; nf++) { o[nf][0]=0.f; o[nf][1]=0.f; o[nf][2]=0.f; o[nf][3]=0.f; }
    float m0 = -INFINITY, m1 = -INFINITY, l0 = 0.f, l1 = 0.f;

    for (int kt = 0; kt < nt; kt++) {
        if (kt + 1 < nt) { CP_WAIT(1); } else { CP_WAIT(0); }
        __syncthreads();   // kv(kt) ready AND all warps finished compute(kt-1)
        if (kt + 2 < nt) {
            att_kv_stage(sb, (kt + 2) % 3, Kp, Vp, (kt + 2) * 64, tid);
            CP_COMMIT();
        }

        const int ktb = kt * 64;
        if (ktb <= qbase + wid * 16 + 15) {
            const uint32_t Ksb = sb + (A_KS + (kt % 3) * 64 * PADH) * 2;
            const uint32_t Vsb = sb + (A_VS + (kt % 3) * 64 * PADH) * 2;

            float s[8][4];
            #pragma unroll
            for (int nf = 0; nf < 8; nf++) { s[nf][0]=0.f; s[nf][1]=0.f; s[nf][2]=0.f; s[nf][3]=0.f; }
            #pragma unroll
            for (int ks = 0; ks < 4; ks++) {
                #pragma unroll
                for (int np = 0; np < 4; np++) {
                    uint32_t bf0[2], bf1[2];
                    ldmx4(bf0[0], bf0[1], bf1[0], bf1[1],
                          Ksb + bkOff + np * 16 * PADB + ks * 32);
                    mma16(s[2*np],   aQ[ks], bf0);
                    mma16(s[2*np+1], aQ[ks], bf1);
                }
            }
            const int r0 = qbase + lr0, r1 = r0 + 8;
            if (ktb + 63 > qbase + wid * 16) {       // diagonal: mask
                #pragma unroll
                for (int nf = 0; nf < 8; nf++) {
                    int c0 = ktb + nf * 8 + 2 * t;
                    if (c0     > r0) s[nf][0] = -INFINITY;
                    if (c0 + 1 > r0) s[nf][1] = -INFINITY;
                    if (c0     > r1) s[nf][2] = -INFINITY;
                    if (c0 + 1 > r1) s[nf][3] = -INFINITY;
                }
            }
            float mx0 = -INFINITY, mx1 = -INFINITY;
            #pragma unroll
            for (int nf = 0; nf < 8; nf++) {
                mx0 = fmaxf(mx0, fmaxf(s[nf][0], s[nf][1]));
                mx1 = fmaxf(mx1, fmaxf(s[nf][2], s[nf][3]));
            }
            mx0 = fmaxf(mx0, __shfl_xor_sync(0xffffffffu, mx0, 1));
            mx0 = fmaxf(mx0, __shfl_xor_sync(0xffffffffu, mx0, 2));
            mx1 = fmaxf(mx1, __shfl_xor_sync(0xffffffffu, mx1, 1));
            mx1 = fmaxf(mx1, __shfl_xor_sync(0xffffffffu, mx1, 2));
            float nm0 = fmaxf(m0, mx0), nm1 = fmaxf(m1, mx1);
            float scl0 = ex2(m0 - nm0), scl1 = ex2(m1 - nm1);

            // exp in-place: s[][] becomes P (stays in registers)
            float ls0 = 0.f, ls1 = 0.f;
            #pragma unroll
            for (int nf = 0; nf < 8; nf++) {
                s[nf][0] = ex2(s[nf][0] - nm0);
                s[nf][1] = ex2(s[nf][1] - nm0);
                s[nf][2] = ex2(s[nf][2] - nm1);
                s[nf][3] = ex2(s[nf][3] - nm1);
                ls0 += s[nf][0] + s[nf][1]; ls1 += s[nf][2] + s[nf][3];
            }
            ls0 += __shfl_xor_sync(0xffffffffu, ls0, 1);
            ls0 += __shfl_xor_sync(0xffffffffu, ls0, 2);
            ls1 += __shfl_xor_sync(0xffffffffu, ls1, 1);
            ls1 += __shfl_xor_sync(0xffffffffu, ls1, 2);
            l0 = l0 * scl0 + ls0; l1 = l1 * scl1 + ls1;
            #pragma unroll
            for (int nf = 0; nf < 8; nf++) {
                o[nf][0] *= scl0; o[nf][1] *= scl0; o[nf][2] *= scl1; o[nf][3] *= scl1;
            }
            // O += P V : P A-frags packed directly from S C-frags (layout identity)
            const int lmq = lid >> 3, lmr = lid & 7;
            #pragma unroll
            for (int ks = 0; ks < 4; ks++) {
                uint32_t ap[4];
                ap[0] = packh2(s[2*ks][0],   s[2*ks][1]);
                ap[1] = packh2(s[2*ks][2],   s[2*ks][3]);
                ap[2] = packh2(s[2*ks+1][0], s[2*ks+1][1]);
                ap[3] = packh2(s[2*ks+1][2], s[2*ks+1][3]);
                #pragma unroll
                for (int nf2 = 0; nf2 < 4; nf2++) {
                    int s_off = ks * 16 + (lmq & 1) * 8 + lmr;
                    int d_off = nf2 * 16 + (lmq >> 1) * 8;
                    uint32_t r0v, r1v, r2v, r3v;
                    ldmx4t(r0v, r1v, r2v, r3v, Vsb + (s_off * PADH + d_off) * 2);
                    uint32_t bfa[2] = { r0v, r1v };
                    uint32_t bfb[2] = { r2v, r3v };
                    mma16(o[nf2 * 2],     ap, bfa);
                    mma16(o[nf2 * 2 + 1], ap, bfb);
                }
            }
            m0 = nm0; m1 = nm1;
        }
    }

    float inv0 = rcpa(l0), inv1 = rcpa(l1);
    #pragma unroll
    for (int nf = 0; nf < 8; nf++) {
        int c = nf * 8 + 2 * t;
        *(__half2*)(O + obase + (size_t)(qbase + lr0) * EE + c) =
            __floats2half2_rn(o[nf][0] * inv0, o[nf][1] * inv0);
        *(__half2*)(O + obase + (size_t)(qbase + lr0 + 8) * EE + c) =
            __floats2half2_rn(o[nf][2] * inv1, o[nf][3] * inv1);
    }
}

// ---------------- launch ------------------------------------------------------
extern "C" void kernel_launch(void* const* d_in, const int* in_sizes, int n_in,
                              void* d_out, int out_size)
{
    const int*   ids   = (const int*)  d_in[0];
    const float* wte   = (const float*)d_in[1];
    const float* wpe   = (const float*)d_in[2];
    const float* wq    = (const float*)d_in[3];
    const float* wk    = (const float*)d_in[4];
    const float* wv    = (const float*)d_in[5];
    const float* bq    = (const float*)d_in[6];
    const float* bk    = (const float*)d_in[7];
    const float* bv    = (const float*)d_in[8];
    const float* wproj = (const float*)d_in[9];
    const float* bproj = (const float*)d_in[10];
    const float* ln1g  = (const float*)d_in[11];
    const float* ln1b  = (const float*)d_in[12];
    const float* ln2g  = (const float*)d_in[13];
    const float* ln2b  = (const float*)d_in[14];
    const float* wfc   = (const float*)d_in[15];
    const float* bfc   = (const float*)d_in[16];
    const float* wout  = (const float*)d_in[17];
    const float* bout  = (const float*)d_in[18];
    float* out = (float*)d_out;

    float *x, *x2, *bqkv;
    __half *h, *qkv, *o, *mb;
    __half *wtqkv, *wtp, *wtfc, *wtout;
    cudaGetSymbolAddress((void**)&x,  g_x);
    cudaGetSymbolAddress((void**)&x2, g_x2);
    cudaGetSymbolAddress((void**)&h,  g_h);
    cudaGetSymbolAddress((void**)&qkv, g_qkv);
    cudaGetSymbolAddress((void**)&o,  g_o);
    cudaGetSymbolAddress((void**)&mb, g_m);
    cudaGetSymbolAddress((void**)&wtqkv, g_wtqkv);
    cudaGetSymbolAddress((void**)&bqkv,  g_bqkv);
    cudaGetSymbolAddress((void**)&wtp,   g_wtp);
    cudaGetSymbolAddress((void**)&wtfc,  g_wtfc);
    cudaGetSymbolAddress((void**)&wtout, g_wtout);

    cudaFuncSetAttribute(attn_tc, cudaFuncAttributeMaxDynamicSharedMemorySize, ATT_SMEM);
    cudaFuncSetAttribute(tc_gemm<false,false,true>,  cudaFuncAttributeMaxDynamicSharedMemorySize, GSMEM);
    cudaFuncSetAttribute(tc_gemm<false,true,false>,  cudaFuncAttributeMaxDynamicSharedMemorySize, GSMEM);
    cudaFuncSetAttribute(tc_gemm<true,false,true>,   cudaFuncAttributeMaxDynamicSharedMemorySize, GSMEM);

    const float alpha = 0.18033688011112042f;   // 0.125 * log2(e)

    // 0. fused prep: embed+ln1 + all weight transposes + bias merge
    prep_kernel<<<20492, 256>>>(ids, wte, wpe, ln1g, ln1b,
                                wq, wk, wv, bq, bk, bv,
                                wproj, wfc, wout,
                                x, h, wtqkv, bqkv, wtp, wtfc, wtout, alpha);
    // 1. merged qkv projection (N=3072)
    tc_gemm<false,false,true><<<GEMM_GRID, 128, GSMEM>>>(h, wtqkv, bqkv, nullptr, qkv, MM, QKVS, EE);
    // 2. causal flash attention
    attn_tc<<<dim3(TT / 128, HH, BB), 256, ATT_SMEM>>>(qkv, o);
    // 3. proj + residual -> x2
    tc_gemm<false,true,false><<<GEMM_GRID, 128, GSMEM>>>(o, wtp, bproj, x, x2, MM, EE, EE);
    // 4. ln2
    ln_kernel<<<MM, 256>>>(x2, ln2g, ln2b, h);
    // 5. fc + gelu -> m
    tc_gemm<true,false,true><<<GEMM_GRID, 128, GSMEM>>>(h, wtfc, bfc, nullptr, mb, MM, FF, EE);
    // 6. out proj + residual -> d_out
    tc_gemm<false,true,false><<<GEMM_GRID, 128, GSMEM>>>(mb, wtout, bout, x2, out, MM, EE, FF);
}